// round 5
// baseline (speedup 1.0000x reference)
#include <cuda_runtime.h>

#define D_COLS   4096
#define K_SEL    2048
#define NTHREADS 128
#define VPT      32               // D_COLS / NTHREADS
#define NWARP    (NTHREADS / 32)  // 4
#define CAND_MAX 128

// Monotone float <-> ordered-uint key mapping (total order matching float <)
__device__ __forceinline__ unsigned fkey(float f) {
    unsigned u = __float_as_uint(f);
    return u ^ ((u & 0x80000000u) ? 0xFFFFFFFFu : 0x80000000u);
}
__device__ __forceinline__ float funkey(unsigned k) {
    unsigned u = k ^ ((k & 0x80000000u) ? 0x80000000u : 0xFFFFFFFFu);
    return __uint_as_float(u);
}
__device__ __forceinline__ bool my_finite(float f) { return fabsf(f) < 3.0e38f; }

// block count of (v >= T); also returns the per-thread 32-bit predicate mask.
__device__ __forceinline__ int block_count_mask(const float* v, float T,
                                                unsigned& bm_out,
                                                int4* s_slot, int lane, int wid)
{
    unsigned b0 = 0, b1 = 0, b2 = 0, b3 = 0;
    #pragma unroll
    for (int i = 0; i < VPT; i += 4) {
        if (v[i+0] >= T) b0 |= (1u << (i+0));
        if (v[i+1] >= T) b1 |= (1u << (i+1));
        if (v[i+2] >= T) b2 |= (1u << (i+2));
        if (v[i+3] >= T) b3 |= (1u << (i+3));
    }
    unsigned bm = (b0 | b1) | (b2 | b3);
    bm_out = bm;
    int cc = __popc(bm);
    cc = __reduce_add_sync(0xffffffffu, cc);
    if (lane == 0) ((int*)s_slot)[wid] = cc;
    __syncthreads();
    int4 p = *s_slot;
    return (p.x + p.y) + (p.z + p.w);
}

__global__ __launch_bounds__(NTHREADS) void sparsify1d_kernel(
    const float* __restrict__ x, float* __restrict__ out)
{
    __shared__ __align__(16) int4  s_redi[2];
    __shared__ __align__(16) float s_redf[NWARP];
    __shared__ float s_thresh;
    __shared__ int   s_ncand;
    __shared__ float s_cand[CAND_MAX];

    const int t    = threadIdx.x;
    const int lane = t & 31;
    const int wid  = t >> 5;
    const long long row = blockIdx.x;

    const float4* __restrict__ xr   = (const float4*)(x + row * (long long)D_COLS);
    float4* __restrict__       orow = (float4*)(out + row * (long long)D_COLS);

    // ---- load row into registers (8 x float4, coalesced) ----
    float v[VPT];
    #pragma unroll
    for (int i = 0; i < 8; i++) {
        float4 f4 = xr[t + i * NTHREADS];
        v[4*i+0] = f4.x; v[4*i+1] = f4.y; v[4*i+2] = f4.z; v[4*i+3] = f4.w;
    }

    // ---- first probe at T0 = 0 (median of N(0,1) row) ----
    unsigned bm0;
    int c0 = block_count_mask(v, 0.0f, bm0, &s_redi[0], lane, wid);

    // ---- bracket: count(>=lo)=clo >= K > chi=count(>=hi)  + predicate masks ----
    float lo, hi; int clo, chi;
    unsigned bmLo, bmHi;
    if (c0 >= K_SEL) {
        lo = 0.0f;  clo = c0;      bmLo = bm0;
        hi = __int_as_float(0x7f800000); chi = 0;  bmHi = 0u;
    } else {
        hi = 0.0f;  chi = c0;      bmHi = bm0;
        lo = __int_as_float(0xff800000); clo = D_COLS; bmLo = 0xFFFFFFFFu;
    }

    float thresh = 0.f;
    bool  have_thresh = false;
    int   par = 1;

    for (int iter = 0; iter < 48; iter++) {
        int m = clo - chi;
        if (m <= CAND_MAX) break;

        unsigned klo = fkey(lo), khi = fkey(hi);
        if (khi - klo <= 1u) { thresh = lo; have_thresh = true; break; }

        float T = lo;
        bool ok = false;
        if (iter < 10) {
            bool lof = my_finite(lo), hif = my_finite(hi);
            if (lof && hif) {
                T = lo + (hi - lo) * ((float)(clo - K_SEL) / (float)m);
            } else if (lof) {
                float dens = (float)D_COLS * 0.39894228f * __expf(-0.5f * lo * lo);
                T = lo + (float)(clo - K_SEL) / dens;
            } else {
                float dens = (float)D_COLS * 0.39894228f * __expf(-0.5f * hi * hi);
                T = hi - (float)(K_SEL - chi) / dens;
            }
            ok = (T > lo) && (T < hi);            // rejects NaN / no-progress
        }
        if (!ok) T = funkey(klo + ((khi - klo) >> 1u));   // guaranteed progress

        unsigned bm;
        int cc = block_count_mask(v, T, bm, &s_redi[par], lane, wid);
        par ^= 1;

        if (cc >= K_SEL) { lo = T; clo = cc; bmLo = bm; }
        else             { hi = T; chi = cc; bmHi = bm; }
    }

    if (!have_thresh) {
        // ---- gather candidates via precomputed masks; pick (K - chi)-th largest ----
        if (t == 0) s_ncand = 0;
        __syncthreads();
        unsigned cm = bmLo & ~bmHi;        // bits of v[] in [lo, hi)
        #pragma unroll
        for (int i = 0; i < VPT; i++) {
            if (cm & (1u << i)) {
                int idx = atomicAdd(&s_ncand, 1);
                if (idx < CAND_MAX) s_cand[idx] = v[i];
            }
        }
        __syncthreads();
        int m = s_ncand;              // == clo - chi  (<= CAND_MAX)
        int j = K_SEL - chi;          // 1-indexed descending rank among candidates
        if (t < m) {
            float vi = s_cand[t];
            int gt = 0, ge = 0;
            for (int c2 = 0; c2 < m; c2++) {
                float fc = s_cand[c2];
                gt += (fc >  vi);
                ge += (fc >= vi);
            }
            if (gt < j && j <= ge) s_thresh = vi;   // ties write identical bits
        }
        __syncthreads();
        thresh = s_thresh;
    }

    // ---- mask in place, masked sum -> scale ----
    float s0 = 0.f, s1 = 0.f, s2 = 0.f, s3 = 0.f;
    #pragma unroll
    for (int i = 0; i < VPT; i += 4) {
        float m0 = (v[i+0] >= thresh) ? v[i+0] : 0.f;
        float m1 = (v[i+1] >= thresh) ? v[i+1] : 0.f;
        float m2 = (v[i+2] >= thresh) ? v[i+2] : 0.f;
        float m3 = (v[i+3] >= thresh) ? v[i+3] : 0.f;
        v[i+0] = m0; v[i+1] = m1; v[i+2] = m2; v[i+3] = m3;
        s0 += m0; s1 += m1; s2 += m2; s3 += m3;
    }
    float s = (s0 + s1) + (s2 + s3);
    s += __shfl_xor_sync(0xffffffffu, s, 16);
    s += __shfl_xor_sync(0xffffffffu, s, 8);
    s += __shfl_xor_sync(0xffffffffu, s, 4);
    s += __shfl_xor_sync(0xffffffffu, s, 2);
    s += __shfl_xor_sync(0xffffffffu, s, 1);
    if (lane == 0) s_redf[wid] = s;
    __syncthreads();
    float4 pf = *(const float4*)s_redf;
    float tot = (pf.x + pf.y) + (pf.z + pf.w);

    float scale = (float)D_COLS / tot;   // out = res / (sum/D) = res * D / sum

    // ---- scale + coalesced store ----
    #pragma unroll
    for (int i = 0; i < 8; i++) {
        float4 o;
        o.x = v[4*i+0] * scale;
        o.y = v[4*i+1] * scale;
        o.z = v[4*i+2] * scale;
        o.w = v[4*i+3] * scale;
        orow[t + i * NTHREADS] = o;
    }
}

extern "C" void kernel_launch(void* const* d_in, const int* in_sizes, int n_in,
                              void* d_out, int out_size)
{
    const float* x = (const float*)d_in[0];
    float* out     = (float*)d_out;
    int rows = in_sizes[0] / D_COLS;     // 16384
    sparsify1d_kernel<<<rows, NTHREADS>>>(x, out);
}

// round 6
// speedup vs baseline: 1.0400x; 1.0400x over previous
#include <cuda_runtime.h>

#define D_COLS   4096
#define K_SEL    2048
#define NTHREADS 128
#define VPT      32               // D_COLS / NTHREADS
#define NWARP    (NTHREADS / 32)  // 4
#define CAND_MAX 32

// Monotone float <-> ordered-uint key mapping (total order matching float <)
__device__ __forceinline__ unsigned fkey(float f) {
    unsigned u = __float_as_uint(f);
    return u ^ ((u & 0x80000000u) ? 0xFFFFFFFFu : 0x80000000u);
}
__device__ __forceinline__ float funkey(unsigned k) {
    unsigned u = k ^ ((k & 0x80000000u) ? 0x80000000u : 0xFFFFFFFFu);
    return __uint_as_float(u);
}
__device__ __forceinline__ bool my_finite(float f) { return fabsf(f) < 3.0e38f; }

// block count of (v >= T): REDUX per warp, lane0 -> smem, one LDS.128 broadcast
__device__ __forceinline__ int block_count(const float* v, float T,
                                           int4* s_slot, int lane, int wid)
{
    int c0 = 0, c1 = 0, c2 = 0, c3 = 0;
    #pragma unroll
    for (int i = 0; i < VPT; i += 4) {
        c0 += (v[i+0] >= T);
        c1 += (v[i+1] >= T);
        c2 += (v[i+2] >= T);
        c3 += (v[i+3] >= T);
    }
    int cc = (c0 + c1) + (c2 + c3);
    cc = __reduce_add_sync(0xffffffffu, cc);
    if (lane == 0) ((int*)s_slot)[wid] = cc;
    __syncthreads();
    int4 p = *s_slot;
    return (p.x + p.y) + (p.z + p.w);
}

__global__ __launch_bounds__(NTHREADS) void sparsify1d_kernel(
    const float* __restrict__ x, float* __restrict__ out)
{
    __shared__ __align__(16) int4  s_redi[2];
    __shared__ __align__(16) float s_redf[NWARP];
    __shared__ float s_thresh;
    __shared__ int   s_ncand;
    __shared__ float s_cand[CAND_MAX];

    const int t    = threadIdx.x;
    const int lane = t & 31;
    const int wid  = t >> 5;
    const long long row = blockIdx.x;

    const float4* __restrict__ xr   = (const float4*)(x + row * (long long)D_COLS);
    float4* __restrict__       orow = (float4*)(out + row * (long long)D_COLS);

    // ---- load row into registers (8 x float4, coalesced) ----
    float v[VPT];
    #pragma unroll
    for (int i = 0; i < 8; i++) {
        float4 f4 = xr[t + i * NTHREADS];
        v[4*i+0] = f4.x; v[4*i+1] = f4.y; v[4*i+2] = f4.z; v[4*i+3] = f4.w;
    }

    // ---- first probe at T0 = 0 (median of N(0,1) row) ----
    int c0 = block_count(v, 0.0f, &s_redi[0], lane, wid);

    // ---- bracket: count(>=lo)=clo >= K > chi=count(>=hi) ----
    float lo, hi; int clo, chi;
    if (c0 >= K_SEL) { lo = 0.0f; clo = c0;  hi = __int_as_float(0x7f800000); chi = 0; }
    else             { hi = 0.0f; chi = c0;  lo = __int_as_float(0xff800000); clo = D_COLS; }

    float thresh = 0.f;
    bool  have_thresh = false;
    int   par = 1;

    for (int iter = 0; iter < 48; iter++) {
        int m = clo - chi;
        if (m <= CAND_MAX) break;

        unsigned klo = fkey(lo), khi = fkey(hi);
        if (khi - klo <= 1u) { thresh = lo; have_thresh = true; break; }

        float T = lo;
        bool ok = false;
        if (iter < 12) {
            bool lof = my_finite(lo), hif = my_finite(hi);
            if (lof && hif) {
                T = lo + (hi - lo) * ((float)(clo - K_SEL) / (float)m);
            } else if (lof) {
                float dens = (float)D_COLS * 0.39894228f * __expf(-0.5f * lo * lo);
                T = lo + (float)(clo - K_SEL) / dens;
            } else {
                float dens = (float)D_COLS * 0.39894228f * __expf(-0.5f * hi * hi);
                T = hi - (float)(K_SEL - chi) / dens;
            }
            ok = (T > lo) && (T < hi);            // rejects NaN / no-progress
        }
        if (!ok) T = funkey(klo + ((khi - klo) >> 1u));   // guaranteed progress

        int cc = block_count(v, T, &s_redi[par], lane, wid);
        par ^= 1;

        if (cc >= K_SEL) { lo = T; clo = cc; }
        else             { hi = T; chi = cc; }
    }

    if (!have_thresh) {
        // ---- gather candidates in [lo, hi); pick exact (K - chi)-th largest ----
        if (t == 0) s_ncand = 0;
        __syncthreads();
        #pragma unroll
        for (int i = 0; i < VPT; i++) {
            float f = v[i];
            if (f >= lo && f < hi) {
                int idx = atomicAdd(&s_ncand, 1);
                if (idx < CAND_MAX) s_cand[idx] = f;
            }
        }
        __syncthreads();
        int m = s_ncand;              // == clo - chi  (<= CAND_MAX = 32)
        int j = K_SEL - chi;          // 1-indexed descending rank among candidates
        if (t < m) {
            float vi = s_cand[t];
            int gt = 0, ge = 0;
            for (int c2 = 0; c2 < m; c2++) {
                float fc = s_cand[c2];
                gt += (fc >  vi);
                ge += (fc >= vi);
            }
            if (gt < j && j <= ge) s_thresh = vi;   // ties write identical bits
        }
        __syncthreads();
        thresh = s_thresh;
    }

    // ---- mask in place, masked sum -> scale ----
    float s0 = 0.f, s1 = 0.f, s2 = 0.f, s3 = 0.f;
    #pragma unroll
    for (int i = 0; i < VPT; i += 4) {
        float m0 = (v[i+0] >= thresh) ? v[i+0] : 0.f;
        float m1 = (v[i+1] >= thresh) ? v[i+1] : 0.f;
        float m2 = (v[i+2] >= thresh) ? v[i+2] : 0.f;
        float m3 = (v[i+3] >= thresh) ? v[i+3] : 0.f;
        v[i+0] = m0; v[i+1] = m1; v[i+2] = m2; v[i+3] = m3;
        s0 += m0; s1 += m1; s2 += m2; s3 += m3;
    }
    float s = (s0 + s1) + (s2 + s3);
    s += __shfl_xor_sync(0xffffffffu, s, 16);
    s += __shfl_xor_sync(0xffffffffu, s, 8);
    s += __shfl_xor_sync(0xffffffffu, s, 4);
    s += __shfl_xor_sync(0xffffffffu, s, 2);
    s += __shfl_xor_sync(0xffffffffu, s, 1);
    if (lane == 0) s_redf[wid] = s;
    __syncthreads();
    float4 pf = *(const float4*)s_redf;
    float tot = (pf.x + pf.y) + (pf.z + pf.w);

    float scale = (float)D_COLS / tot;   // out = res / (sum/D) = res * D / sum

    // ---- scale + coalesced store ----
    #pragma unroll
    for (int i = 0; i < 8; i++) {
        float4 o;
        o.x = v[4*i+0] * scale;
        o.y = v[4*i+1] * scale;
        o.z = v[4*i+2] * scale;
        o.w = v[4*i+3] * scale;
        orow[t + i * NTHREADS] = o;
    }
}

extern "C" void kernel_launch(void* const* d_in, const int* in_sizes, int n_in,
                              void* d_out, int out_size)
{
    const float* x = (const float*)d_in[0];
    float* out     = (float*)d_out;
    int rows = in_sizes[0] / D_COLS;     // 16384
    sparsify1d_kernel<<<rows, NTHREADS>>>(x, out);
}

// round 7
// speedup vs baseline: 1.0612x; 1.0204x over previous
#include <cuda_runtime.h>

#define D_COLS   4096
#define K_SEL    2048
#define NTHREADS 128
#define VPT      32               // D_COLS / NTHREADS
#define NWARP    (NTHREADS / 32)  // 4
#define CAND_MAX 32

#define F_PINF  __int_as_float(0x7f800000)
#define F_NINF  __int_as_float(0xff800000)
#define INV_DENS0 6.119698e-4f    // 1 / (4096 * 0.39894228)

// Monotone float <-> ordered-uint key mapping (total order matching float <)
__device__ __forceinline__ unsigned fkey(float f) {
    unsigned u = __float_as_uint(f);
    return u ^ ((u & 0x80000000u) ? 0xFFFFFFFFu : 0x80000000u);
}
__device__ __forceinline__ float funkey(unsigned k) {
    unsigned u = k ^ ((k & 0x80000000u) ? 0x80000000u : 0xFFFFFFFFu);
    return __uint_as_float(u);
}
__device__ __forceinline__ bool my_finite(float f) { return fabsf(f) < 3.0e38f; }

// block count of (v >= T): REDUX per warp, lane0 -> smem slot, LDS.128 broadcast
__device__ __forceinline__ int block_count(const float* v, float T,
                                           int4* s_slot, int lane, int wid)
{
    int c0 = 0, c1 = 0, c2 = 0, c3 = 0;
    #pragma unroll
    for (int i = 0; i < VPT; i += 4) {
        c0 += (v[i+0] >= T);
        c1 += (v[i+1] >= T);
        c2 += (v[i+2] >= T);
        c3 += (v[i+3] >= T);
    }
    int cc = (c0 + c1) + (c2 + c3);
    cc = __reduce_add_sync(0xffffffffu, cc);
    if (lane == 0) ((int*)s_slot)[wid] = cc;
    __syncthreads();
    int4 p = *s_slot;
    return (p.x + p.y) + (p.z + p.w);
}

__global__ __launch_bounds__(NTHREADS) void sparsify1d_kernel(
    const float* __restrict__ x, float* __restrict__ out)
{
    __shared__ __align__(16) int4  s_redi[2];
    __shared__ __align__(16) float s_redf[NWARP];
    __shared__ float s_thresh;
    __shared__ float s_csum;
    __shared__ int   s_ncand;
    __shared__ float s_cand[CAND_MAX];

    const int t    = threadIdx.x;
    const int lane = t & 31;
    const int wid  = t >> 5;
    const long long row = blockIdx.x;

    const float4* __restrict__ xr   = (const float4*)(x + row * (long long)D_COLS);
    float4* __restrict__       orow = (float4*)(out + row * (long long)D_COLS);

    // ---- load row into registers (8 x float4, coalesced) ----
    float v[VPT];
    #pragma unroll
    for (int i = 0; i < 8; i++) {
        float4 f4 = xr[t + i * NTHREADS];
        v[4*i+0] = f4.x; v[4*i+1] = f4.y; v[4*i+2] = f4.z; v[4*i+3] = f4.w;
    }
    if (t == 0) s_ncand = 0;      // published by pass A's barrier

    // ---- pass A: probe at 0; pass B: Newton probe (unconditional) ----
    int   cA = block_count(v, 0.0f, &s_redi[0], lane, wid);
    float T1 = (float)(cA - K_SEL) * INV_DENS0;
    int   cB = block_count(v, T1,   &s_redi[1], lane, wid);

    // ---- build bracket: count(>=lo)=clo >= K > chi=count(>=hi) ----
    float lo = F_NINF, hi = F_PINF;
    int clo = D_COLS, chi = 0;
    if (cA >= K_SEL) { lo = 0.0f; clo = cA; } else { hi = 0.0f; chi = cA; }
    if (T1 > lo && T1 < hi) {
        if (cB >= K_SEL) { lo = T1; clo = cB; } else { hi = T1; chi = cB; }
    }

    float thresh = 0.f;
    bool  have_thresh = false;
    int   par = 0;

    // ---- fallback refinement loop (usually 0 iterations) ----
    for (int iter = 0; iter < 32; iter++) {
        int m = clo - chi;
        if (m <= CAND_MAX) break;

        unsigned klo = fkey(lo), khi = fkey(hi);
        if (khi - klo <= 1u) { thresh = lo; have_thresh = true; break; }

        bool lof = my_finite(lo), hif = my_finite(hi);
        float stepl = (float)(clo - K_SEL) + 0.5f;
        float steph = (float)(K_SEL - chi) + 0.5f;
        float Ti = lo + (hi - lo) * (stepl / (float)m);
        float Tl = lo + stepl / (1634.07f * __expf(-0.5f * lo * lo));
        float Th = hi - steph / (1634.07f * __expf(-0.5f * hi * hi));
        float T  = (lof && hif) ? Ti : (lof ? Tl : Th);
        bool ok  = (T > lo) && (T < hi) && (iter < 12);
        if (!ok) T = funkey(klo + ((khi - klo) >> 1u));   // guaranteed progress

        int cc = block_count(v, T, &s_redi[par], lane, wid);
        par ^= 1;
        if (cc >= K_SEL) { lo = T; clo = cc; }
        else             { hi = T; chi = cc; }
    }

    float total;
    if (!have_thresh) {
        // ---- single sweep: gather candidates in [lo,hi) + sum of v>=hi ----
        float ssel = 0.f;
        #pragma unroll
        for (int i = 0; i < VPT; i++) {
            float f = v[i];
            if (f >= hi) {
                ssel += f;
            } else if (f >= lo) {
                int idx = atomicAdd(&s_ncand, 1);
                if (idx < CAND_MAX) s_cand[idx] = f;
            }
        }
        ssel += __shfl_xor_sync(0xffffffffu, ssel, 16);
        ssel += __shfl_xor_sync(0xffffffffu, ssel, 8);
        ssel += __shfl_xor_sync(0xffffffffu, ssel, 4);
        ssel += __shfl_xor_sync(0xffffffffu, ssel, 2);
        ssel += __shfl_xor_sync(0xffffffffu, ssel, 1);
        if (lane == 0) s_redf[wid] = ssel;
        __syncthreads();
        float4 pf = *(const float4*)s_redf;
        float ssel_total = (pf.x + pf.y) + (pf.z + pf.w);

        // ---- warp 0: bitonic sort of <=32 candidates, pick j-th largest ----
        if (wid == 0) {
            int m2 = s_ncand;             // == clo - chi  (<= 32)
            int j  = K_SEL - chi;         // 1-indexed descending rank
            float val = (lane < m2) ? s_cand[lane] : F_NINF;
            #pragma unroll
            for (int k = 2; k <= 32; k <<= 1) {
                #pragma unroll
                for (int jj = k >> 1; jj > 0; jj >>= 1) {
                    float other = __shfl_xor_sync(0xffffffffu, val, jj);
                    bool up    = ((lane & k)  == 0);
                    bool lower = ((lane & jj) == 0);
                    float mn = fminf(val, other), mx = fmaxf(val, other);
                    val = (up == lower) ? mn : mx;   // ascending sort
                }
            }
            float th = __shfl_sync(0xffffffffu, val, 32 - j);  // j-th largest
            float cs = (val >= th) ? val : 0.f;    // -inf padding excluded
            cs += __shfl_xor_sync(0xffffffffu, cs, 16);
            cs += __shfl_xor_sync(0xffffffffu, cs, 8);
            cs += __shfl_xor_sync(0xffffffffu, cs, 4);
            cs += __shfl_xor_sync(0xffffffffu, cs, 2);
            cs += __shfl_xor_sync(0xffffffffu, cs, 1);
            if (lane == 0) { s_thresh = th; s_csum = cs; }
        }
        __syncthreads();
        thresh = s_thresh;
        total  = ssel_total + s_csum;
    } else {
        // ---- rare path: thresh known exactly; plain masked sum ----
        float ss = 0.f;
        #pragma unroll
        for (int i = 0; i < VPT; i++) ss += (v[i] >= thresh) ? v[i] : 0.f;
        ss += __shfl_xor_sync(0xffffffffu, ss, 16);
        ss += __shfl_xor_sync(0xffffffffu, ss, 8);
        ss += __shfl_xor_sync(0xffffffffu, ss, 4);
        ss += __shfl_xor_sync(0xffffffffu, ss, 2);
        ss += __shfl_xor_sync(0xffffffffu, ss, 1);
        if (lane == 0) s_redf[wid] = ss;
        __syncthreads();
        float4 pf = *(const float4*)s_redf;
        total = (pf.x + pf.y) + (pf.z + pf.w);
    }

    float scale = (float)D_COLS / total;   // out = res * D / sum(res)

    // ---- final predicated scale + coalesced store ----
    #pragma unroll
    for (int i = 0; i < 8; i++) {
        float4 o;
        o.x = (v[4*i+0] >= thresh) ? v[4*i+0] * scale : 0.f;
        o.y = (v[4*i+1] >= thresh) ? v[4*i+1] * scale : 0.f;
        o.z = (v[4*i+2] >= thresh) ? v[4*i+2] * scale : 0.f;
        o.w = (v[4*i+3] >= thresh) ? v[4*i+3] * scale : 0.f;
        orow[t + i * NTHREADS] = o;
    }
}

extern "C" void kernel_launch(void* const* d_in, const int* in_sizes, int n_in,
                              void* d_out, int out_size)
{
    const float* x = (const float*)d_in[0];
    float* out     = (float*)d_out;
    int rows = in_sizes[0] / D_COLS;     // 16384
    sparsify1d_kernel<<<rows, NTHREADS>>>(x, out);
}

// round 8
// speedup vs baseline: 1.1559x; 1.0892x over previous
#include <cuda_runtime.h>

#define D_COLS   4096
#define K_SEL    2048
#define NTHREADS 128
#define VPT      32               // D_COLS / NTHREADS
#define NWARP    (NTHREADS / 32)  // 4
#define CAND_MAX 32

#define F_PINF  __int_as_float(0x7f800000)
#define F_NINF  __int_as_float(0xff800000)
#define DENS0     1634.07f        // 4096 * phi(0) = 4096 * 0.39894228
#define INV_DENS0 6.119698e-4f    // 1 / DENS0
#define MARGIN    16.5f

// Monotone float <-> ordered-uint key mapping (total order matching float <)
__device__ __forceinline__ unsigned fkey(float f) {
    unsigned u = __float_as_uint(f);
    return u ^ ((u & 0x80000000u) ? 0xFFFFFFFFu : 0x80000000u);
}
__device__ __forceinline__ float funkey(unsigned k) {
    unsigned u = k ^ ((k & 0x80000000u) ? 0x80000000u : 0xFFFFFFFFu);
    return __uint_as_float(u);
}
__device__ __forceinline__ bool my_finite(float f) { return fabsf(f) < 3.0e38f; }

// block count of (v >= T): REDUX per warp, lane0 -> smem slot, LDS.128 broadcast
__device__ __forceinline__ int block_count(const float* v, float T,
                                           int4* s_slot, int lane, int wid)
{
    int c0 = 0, c1 = 0, c2 = 0, c3 = 0;
    #pragma unroll
    for (int i = 0; i < VPT; i += 4) {
        c0 += (v[i+0] >= T);
        c1 += (v[i+1] >= T);
        c2 += (v[i+2] >= T);
        c3 += (v[i+3] >= T);
    }
    int cc = (c0 + c1) + (c2 + c3);
    cc = __reduce_add_sync(0xffffffffu, cc);
    if (lane == 0) ((int*)s_slot)[wid] = cc;
    __syncthreads();
    int4 p = *s_slot;
    return (p.x + p.y) + (p.z + p.w);
}

__global__ __launch_bounds__(NTHREADS) void sparsify1d_kernel(
    const float* __restrict__ x, float* __restrict__ out)
{
    __shared__ __align__(16) int4  s_redi[2];
    __shared__ __align__(16) float s_redf[NWARP];
    __shared__ float s_thresh;
    __shared__ float s_csum;
    __shared__ int   s_ncand;
    __shared__ float s_cand[CAND_MAX];

    const int t    = threadIdx.x;
    const int lane = t & 31;
    const int wid  = t >> 5;
    const long long row = blockIdx.x;

    const float4* __restrict__ xr   = (const float4*)(x + row * (long long)D_COLS);
    float4* __restrict__       orow = (float4*)(out + row * (long long)D_COLS);

    // ---- load row into registers (8 x float4, coalesced) ----
    float v[VPT];
    #pragma unroll
    for (int i = 0; i < 8; i++) {
        float4 f4 = xr[t + i * NTHREADS];
        v[4*i+0] = f4.x; v[4*i+1] = f4.y; v[4*i+2] = f4.z; v[4*i+3] = f4.w;
    }
    if (t == 0) s_ncand = 0;      // published by probe A's barrier

    // ---- probe A at 0 (median of N(0,1) row); probe B = Newton step ----
    int   cA = block_count(v, 0.0f, &s_redi[0], lane, wid);
    float T1 = (float)(cA - K_SEL) * INV_DENS0;
    int   cB = block_count(v, T1,   &s_redi[1], lane, wid);

    // ---- build bracket: count(>=lo)=clo >= K > chi=count(>=hi) ----
    float lo = F_NINF, hi = F_PINF;
    int clo = D_COLS, chi = 0;
    if (cA >= K_SEL) { lo = 0.0f; clo = cA; } else { hi = 0.0f; chi = cA; }
    if (T1 > lo && T1 < hi) {
        if (cB >= K_SEL) { lo = T1; clo = cB; } else { hi = T1; chi = cB; }
    }

    // ---- probe C: margin-targeted (aims count K -/+ MARGIN from nearer end) ----
    if (clo - chi > CAND_MAX) {
        float d_lo = (float)(clo - K_SEL);
        float d_hi = (float)(K_SEL - chi);
        bool fromLo = d_lo <= d_hi;
        float e  = fromLo ? lo : hi;
        float dd = fromLo ? d_lo : d_hi;
        float inv_dens = __expf(0.5f * e * e) * INV_DENS0;
        float step = (dd + MARGIN) * inv_dens;
        float T2 = fromLo ? (lo + step) : (hi - step);
        if (T2 > lo && T2 < hi) {
            int c2 = block_count(v, T2, &s_redi[0], lane, wid);
            if (c2 >= K_SEL) { lo = T2; clo = c2; }
            else             { hi = T2; chi = c2; }
        }
    }

    float thresh = 0.f;
    bool  have_thresh = false;
    int   par = 1;

    // ---- fallback refinement loop (rare) ----
    for (int iter = 0; iter < 48; iter++) {
        int m = clo - chi;
        if (m <= CAND_MAX) break;

        unsigned klo = fkey(lo), khi = fkey(hi);
        if (khi - klo <= 1u) { thresh = lo; have_thresh = true; break; }

        bool lof = my_finite(lo), hif = my_finite(hi);
        float stepl = (float)(clo - K_SEL) + 0.5f;
        float steph = (float)(K_SEL - chi) + 0.5f;
        float Ti = lo + (hi - lo) * (stepl / (float)m);
        float Tl = lo + stepl / (DENS0 * __expf(-0.5f * lo * lo));
        float Th = hi - steph / (DENS0 * __expf(-0.5f * hi * hi));
        float T  = (lof && hif) ? Ti : (lof ? Tl : Th);
        bool ok  = (T > lo) && (T < hi) && (iter < 12);
        if (!ok) T = funkey(klo + ((khi - klo) >> 1u));   // guaranteed progress

        int cc = block_count(v, T, &s_redi[par], lane, wid);
        par ^= 1;
        if (cc >= K_SEL) { lo = T; clo = cc; }
        else             { hi = T; chi = cc; }
    }

    float total;
    if (!have_thresh) {
        // ---- single sweep: predicated sum of v>=hi + warp-guarded gather ----
        float ssel = 0.f;
        #pragma unroll
        for (int i = 0; i < VPT; i++) {
            float f = v[i];
            ssel += (f >= hi) ? f : 0.f;
            bool inr = (f >= lo) && (f < hi);
            if (__any_sync(0xffffffffu, inr)) {     // warp-uniform skip
                if (inr) {
                    int idx = atomicAdd(&s_ncand, 1);
                    if (idx < CAND_MAX) s_cand[idx] = f;
                }
            }
        }
        ssel += __shfl_xor_sync(0xffffffffu, ssel, 16);
        ssel += __shfl_xor_sync(0xffffffffu, ssel, 8);
        ssel += __shfl_xor_sync(0xffffffffu, ssel, 4);
        ssel += __shfl_xor_sync(0xffffffffu, ssel, 2);
        ssel += __shfl_xor_sync(0xffffffffu, ssel, 1);
        if (lane == 0) s_redf[wid] = ssel;
        __syncthreads();
        float4 pf = *(const float4*)s_redf;
        float ssel_total = (pf.x + pf.y) + (pf.z + pf.w);

        // ---- warp 0: bitonic sort of <=32 candidates, pick j-th largest ----
        if (wid == 0) {
            int m2 = s_ncand;             // == clo - chi  (<= 32)
            int j  = K_SEL - chi;         // 1-indexed descending rank
            float val = (lane < m2) ? s_cand[lane] : F_NINF;
            #pragma unroll
            for (int k = 2; k <= 32; k <<= 1) {
                #pragma unroll
                for (int jj = k >> 1; jj > 0; jj >>= 1) {
                    float other = __shfl_xor_sync(0xffffffffu, val, jj);
                    bool up    = ((lane & k)  == 0);
                    bool lower = ((lane & jj) == 0);
                    float mn = fminf(val, other), mx = fmaxf(val, other);
                    val = (up == lower) ? mn : mx;   // ascending sort
                }
            }
            float th = __shfl_sync(0xffffffffu, val, 32 - j);  // j-th largest
            float cs = (val >= th) ? val : 0.f;    // -inf padding excluded
            cs += __shfl_xor_sync(0xffffffffu, cs, 16);
            cs += __shfl_xor_sync(0xffffffffu, cs, 8);
            cs += __shfl_xor_sync(0xffffffffu, cs, 4);
            cs += __shfl_xor_sync(0xffffffffu, cs, 2);
            cs += __shfl_xor_sync(0xffffffffu, cs, 1);
            if (lane == 0) { s_thresh = th; s_csum = cs; }
        }
        __syncthreads();
        thresh = s_thresh;
        total  = ssel_total + s_csum;
    } else {
        // ---- rare path: thresh known exactly; plain masked sum ----
        float ss = 0.f;
        #pragma unroll
        for (int i = 0; i < VPT; i++) ss += (v[i] >= thresh) ? v[i] : 0.f;
        ss += __shfl_xor_sync(0xffffffffu, ss, 16);
        ss += __shfl_xor_sync(0xffffffffu, ss, 8);
        ss += __shfl_xor_sync(0xffffffffu, ss, 4);
        ss += __shfl_xor_sync(0xffffffffu, ss, 2);
        ss += __shfl_xor_sync(0xffffffffu, ss, 1);
        if (lane == 0) s_redf[wid] = ss;
        __syncthreads();
        float4 pf = *(const float4*)s_redf;
        total = (pf.x + pf.y) + (pf.z + pf.w);
    }

    float scale = (float)D_COLS / total;   // out = res * D / sum(res)

    // ---- final predicated scale + coalesced store ----
    #pragma unroll
    for (int i = 0; i < 8; i++) {
        float4 o;
        o.x = (v[4*i+0] >= thresh) ? v[4*i+0] * scale : 0.f;
        o.y = (v[4*i+1] >= thresh) ? v[4*i+1] * scale : 0.f;
        o.z = (v[4*i+2] >= thresh) ? v[4*i+2] * scale : 0.f;
        o.w = (v[4*i+3] >= thresh) ? v[4*i+3] * scale : 0.f;
        orow[t + i * NTHREADS] = o;
    }
}

extern "C" void kernel_launch(void* const* d_in, const int* in_sizes, int n_in,
                              void* d_out, int out_size)
{
    const float* x = (const float*)d_in[0];
    float* out     = (float*)d_out;
    int rows = in_sizes[0] / D_COLS;     // 16384
    sparsify1d_kernel<<<rows, NTHREADS>>>(x, out);
}